// round 11
// baseline (speedup 1.0000x reference)
#include <cuda_runtime.h>
#include <cstdint>

#define TPB        256        // 8 warps: 4 warps per row, 2 rows per tile
#define TR         2          // rows per tile
#define G_BLOCKS   888        // 6 blocks/SM * 148 SMs

__device__ double   g_loss[2];   // [0]=succ sum, [1]=pred sum
__device__ int      g_cnt;       // sum(line_mask)
__device__ int      g_lbl64;     // 1 if labels are int64, 0 if int32
__device__ int      g_mask32;    // 1 if mask is int32, 0 if uint8
__device__ unsigned g_done;      // completed-block ticket

// ---------------------------------------------------------------------------
// init: zero accumulators + detect label width (int64 vs int32) and mask
// width (int32 vs uint8). Parallel — the serial version cost 547us.
// ---------------------------------------------------------------------------
__global__ void __launch_bounds__(256)
init_kernel(const int* __restrict__ label_words,
            const unsigned char* __restrict__ mask_bytes,
            int BN) {
    __shared__ int sh_not64;
    __shared__ unsigned sh_any;
    __shared__ unsigned sh_odd;

    const int tid = threadIdx.x;
    if (tid == 0) {
        g_loss[0] = 0.0; g_loss[1] = 0.0;
        g_cnt = 0; g_done = 0u;
        sh_not64 = 0; sh_any = 0u; sh_odd = 0u;
    }
    __syncthreads();

    if (tid < 128) {
        int lo = label_words[2 * tid];
        int hi = label_words[2 * tid + 1];
        bool ok = (hi == 0 && lo >= 0) || (hi == -1 && lo == -1);
        if (!ok) atomicOr(&sh_not64, 1);
    }
    {
        const uint4* m4 = (const uint4*)mask_bytes;
        const int words4 = BN / 16;
        unsigned my_all = 0u, my_odd = 0u;
        for (int k = tid; k < words4; k += 256) {
            uint4 v = m4[k];
            unsigned all = v.x | v.y | v.z | v.w;
            my_all |= all;
            my_odd |= (all & 0xFFFFFF00u);
        }
        for (int o = 16; o; o >>= 1) {
            my_all |= __shfl_xor_sync(0xffffffffu, my_all, o);
            my_odd |= __shfl_xor_sync(0xffffffffu, my_odd, o);
        }
        if ((tid & 31) == 0) {
            if (my_all) atomicOr(&sh_any, 1u);
            if (my_odd) atomicOr(&sh_odd, 1u);
        }
    }
    __syncthreads();
    if (tid == 0) {
        g_lbl64  = sh_not64 ? 0 : 1;
        g_mask32 = (sh_any && !sh_odd) ? 1 : 0;
    }
}

// ------------------------- PTX helpers -------------------------------------
__device__ __forceinline__ uint32_t smem_u32(const void* p) {
    uint32_t a;
    asm("{ .reg .u64 t; cvta.to.shared.u64 t, %1; cvt.u32.u64 %0, t; }"
        : "=r"(a) : "l"(p));
    return a;
}
__device__ __forceinline__ void mbar_init(uint32_t a, uint32_t c) {
    asm volatile("mbarrier.init.shared.b64 [%0], %1;" :: "r"(a), "r"(c) : "memory");
}
__device__ __forceinline__ void mbar_expect_tx(uint32_t a, uint32_t tx) {
    asm volatile("mbarrier.arrive.expect_tx.shared.b64 _, [%0], %1;"
                 :: "r"(a), "r"(tx) : "memory");
}
__device__ __forceinline__ void mbar_wait(uint32_t a, uint32_t ph) {
    asm volatile(
        "{\n\t"
        ".reg .pred P;\n\t"
        "WAIT_%=:\n\t"
        "mbarrier.try_wait.parity.acquire.cta.shared::cta.b64 P, [%0], %1, 0x989680;\n\t"
        "@P bra.uni DONE_%=;\n\t"
        "bra.uni WAIT_%=;\n\t"
        "DONE_%=:\n\t"
        "}"
        :: "r"(a), "r"(ph) : "memory");
}
__device__ __forceinline__ void bulk_g2s(uint32_t dst, const void* src,
                                         uint32_t bytes, uint32_t mbar) {
    asm volatile(
        "cp.async.bulk.shared::cluster.global.mbarrier::complete_tx::bytes "
        "[%0], [%1], %2, [%3];"
        :: "r"(dst), "l"(src), "r"(bytes), "r"(mbar) : "memory");
}
__device__ __forceinline__ void fence_proxy_async_cta() {
    asm volatile("fence.proxy.async.shared::cta;" ::: "memory");
}

__device__ __forceinline__ void block_epilogue(float l0, float l1, int cnt,
                                               const float* w, float* out,
                                               unsigned nblocks) {
    if (threadIdx.x == 0) {
        if (l0 != 0.f) atomicAdd(&g_loss[0], (double)l0);
        if (l1 != 0.f) atomicAdd(&g_loss[1], (double)l1);
        if (cnt)       atomicAdd(&g_cnt, cnt);
        __threadfence();
        unsigned t = atomicAdd(&g_done, 1u);
        if (t == nblocks - 1u) {
            double denom = (g_cnt > 0) ? (double)g_cnt : 1.0;
            float succ = (float)(g_loss[0] / denom);
            float pred = (float)(g_loss[1] / denom);
            out[0] = succ + (*w) * pred;
            out[1] = succ;
            out[2] = pred;
            out[3] = (float)g_cnt;
        }
    }
}

// ---------------------------------------------------------------------------
// R11: 4-stage pipeline (R10) + 8 warps/block (R9). R10 regressed because
// 128-thr blocks halved warps/SM (24, occ 35%) and compute stopped fitting
// under the copies. Now: 8 warps per 2-row tile -> QUARTER-row per warp
// (K2 float4/lane), 32 KB smem -> 6 blocks/SM -> 48 warps/SM AND 3 tiles of
// copy slack (24 KB in flight per block). Labels/mask prefetched before the
// stage wait; partials combine 4-wide in shared.
// ---------------------------------------------------------------------------
template <int NCOLS, int NS>
__global__ void __launch_bounds__(TPB)
loss_kernel_tma(const float* __restrict__ slog, const void* __restrict__ slab,
                const float* __restrict__ plog, const void* __restrict__ plab,
                const unsigned char* __restrict__ mask, int BN,
                const float* __restrict__ w, float* __restrict__ out,
                int ntiles) {
    __shared__ __align__(16) float st[NS][TR][NCOLS];
    __shared__ __align__(8)  unsigned long long mbar[NS];
    __shared__ float sh_sum[TPB / 32];
    __shared__ float sh_max[TPB / 32];
    __shared__ float sh_loss[2];
    __shared__ int   sh_cnt;

    const int tid  = threadIdx.x;
    const int wid  = tid >> 5;
    const int lane = tid & 31;
    const int j    = wid >> 2;      // row within tile (0..TR-1)
    const int q    = wid & 3;       // quarter within row (0..3)

    constexpr int      K2         = NCOLS / 512;        // float4/lane/quarter
    constexpr uint32_t TILE_BYTES = TR * NCOLS * 4;
    const int tilesPerTensor = ntiles >> 1;

    uint32_t mb[NS], stb[NS];
#pragma unroll
    for (int s = 0; s < NS; s++) {
        mb[s]  = smem_u32(&mbar[s]);
        stb[s] = smem_u32(&st[s][0][0]);
    }

    if (tid == 0) {
        sh_loss[0] = 0.f; sh_loss[1] = 0.f; sh_cnt = 0;
#pragma unroll
        for (int s = 0; s < NS; s++) mbar_init(mb[s], 1);
    }
    __syncthreads();

    const bool l64 = (g_lbl64 != 0);
    const bool m32 = (g_mask32 != 0);

    // prologue: fill all stages
    if (tid == 0) {
#pragma unroll
        for (int s = 0; s < NS; s++) {
            int t = blockIdx.x + s * (int)gridDim.x;
            if (t < ntiles) {
                const float* src = (t < tilesPerTensor)
                    ? slog + (size_t)t * (TR * NCOLS)
                    : plog + (size_t)(t - tilesPerTensor) * (TR * NCOLS);
                mbar_expect_tx(mb[s], TILE_BYTES);
                bulk_g2s(stb[s], src, TILE_BYTES, mb[s]);
            }
        }
    }

    int it = 0;
    for (int t = blockIdx.x; t < ntiles; t += gridDim.x, it++) {
        const int      s      = it % NS;
        const uint32_t parity = (uint32_t)((it / NS) & 1);

        const int dir   = (t < tilesPerTensor) ? 0 : 1;
        const int rbase = (dir ? (t - tilesPerTensor) : t) * TR;
        const int r     = rbase + j;
        const int i     = r & (NCOLS - 1);

        // prefetch scalars BEFORE the stage wait
        int lbl;
        if (l64) lbl = (int)((const long long*)(dir ? plab : slab))[r];
        else     lbl = ((const int*)(dir ? plab : slab))[r];
        const bool active = m32 ? (((const int*)mask)[r] != 0) : (mask[r] != 0);
        const bool self   = active && (lbl < 0);

        mbar_wait(mb[s], parity);

        // target logit from smem (row is staged)
        float tvx = 0.f;
        if (active && q == 0 && lane == 0)
            tvx = st[s][j][(lbl < 0) ? i : lbl];

        const float4* rp =
            reinterpret_cast<const float4*>(&st[s][j][q * (NCOLS / 4)]);

        // ---- pass 1 partials (quarter-row per warp) ----
        if (active) {
            if (!self) {
                float s0 = 0.f, s1 = 0.f;
#pragma unroll
                for (int k = 0; k < K2; k++) {
                    float4 v = rp[k * 32 + lane];
                    s0 += __expf(v.x) + __expf(v.y);
                    s1 += __expf(v.z) + __expf(v.w);
                }
                float ss = s0 + s1;
#pragma unroll
                for (int o = 16; o; o >>= 1)
                    ss += __shfl_xor_sync(0xffffffffu, ss, o);
                if (lane == 0) sh_sum[wid] = ss;
            } else {
                float mx = -3.402823466e38f;
#pragma unroll
                for (int k = 0; k < K2; k++) {
                    float4 v = rp[k * 32 + lane];
                    mx = fmaxf(mx, fmaxf(fmaxf(v.x, v.y), fmaxf(v.z, v.w)));
                }
#pragma unroll
                for (int o = 16; o; o >>= 1)
                    mx = fmaxf(mx, __shfl_xor_sync(0xffffffffu, mx, o));
                if (lane == 0) sh_max[wid] = mx;
            }
        }
        __syncthreads();   // sync1

        // ---- pass 2: self rows, shifted sum with combined row max ----
        if (self) {
            const int b = j << 2;
            float mx = fmaxf(fmaxf(sh_max[b], sh_max[b + 1]),
                             fmaxf(sh_max[b + 2], sh_max[b + 3]));
            float ss = 0.f;
#pragma unroll
            for (int k = 0; k < K2; k++) {
                float4 v = rp[k * 32 + lane];
                ss += __expf(v.x - mx) + __expf(v.y - mx) +
                      __expf(v.z - mx) + __expf(v.w - mx);
            }
#pragma unroll
            for (int o = 16; o; o >>= 1)
                ss += __shfl_xor_sync(0xffffffffu, ss, o);
            if (lane == 0) sh_sum[wid] = ss;
        }
        __syncthreads();   // sync2 — stage s fully consumed

        // ---- refill stage s with tile t + NS*gridDim.x ----
        if (tid == 0) {
            int t2 = t + NS * (int)gridDim.x;
            if (t2 < ntiles) {
                const float* src = (t2 < tilesPerTensor)
                    ? slog + (size_t)t2 * (TR * NCOLS)
                    : plog + (size_t)(t2 - tilesPerTensor) * (TR * NCOLS);
                fence_proxy_async_cta();
                mbar_expect_tx(mb[s], TILE_BYTES);
                bulk_g2s(stb[s], src, TILE_BYTES, mb[s]);
            }
        }

        // ---- lead warp of each row finalizes (reads only sh_sum/sh_max) ----
        if (active && q == 0 && lane == 0) {
            const int b = j << 2;
            float S = (sh_sum[b] + sh_sum[b + 1]) + (sh_sum[b + 2] + sh_sum[b + 3]);
            float nll;
            if (!self) {
                nll = __logf(S) - tvx;
            } else {
                float mx = fmaxf(fmaxf(sh_max[b], sh_max[b + 1]),
                                 fmaxf(sh_max[b + 2], sh_max[b + 3]));
                // diagonal := rowmax+1, label := i:
                // nll = log(1 + e^{-1} * (S - e^{x_i - M}))
                float rest = fmaxf(S - __expf(tvx - mx), 0.0f);
                nll = __logf(1.0f + 0.36787944117144233f * rest);
            }
            atomicAdd(&sh_loss[dir], nll);
            if (dir == 0) atomicAdd(&sh_cnt, 1);
        }
        // next iteration's mbar_wait + sync1 order everything else
    }
    __syncthreads();
    block_epilogue(sh_loss[0], sh_loss[1], sh_cnt, w, out, gridDim.x);
}

// ---------------------------------------------------------------------------
// Generic fallback (any N): two strided passes via global loads.
// ---------------------------------------------------------------------------
__global__ void __launch_bounds__(256)
loss_kernel_generic(const float* __restrict__ slog, const void* __restrict__ slab,
                    const float* __restrict__ plog, const void* __restrict__ plab,
                    const unsigned char* __restrict__ mask, int N, int BN,
                    const float* __restrict__ w, float* __restrict__ out) {
    __shared__ float sh_loss[2];
    __shared__ int   sh_cnt;
    if (threadIdx.x == 0) { sh_loss[0] = 0.f; sh_loss[1] = 0.f; sh_cnt = 0; }
    __syncthreads();

    const int lane = threadIdx.x & 31;
    const int warp = blockIdx.x * 8 + (threadIdx.x >> 5);

    if (warp < 2 * BN) {
        const int dir = (warp >= BN) ? 1 : 0;
        const int r   = dir ? warp - BN : warp;
        const int i   = r % N;

        const float* logits = (dir ? plog : slog) + (size_t)r * N;
        int lbl;
        if (g_lbl64) lbl = (int)((const long long*)(dir ? plab : slab))[r];
        else         lbl = ((const int*)(dir ? plab : slab))[r];
        const bool active = g_mask32 ? (((const int*)mask)[r] != 0) : (mask[r] != 0);

        if (active) {
            const bool self = (lbl < 0);
            const int  tgt  = self ? i : lbl;

            float mx = -3.402823466e38f;
            for (int jx = lane; jx < N; jx += 32) mx = fmaxf(mx, logits[jx]);
            for (int o = 16; o; o >>= 1)
                mx = fmaxf(mx, __shfl_xor_sync(0xffffffffu, mx, o));

            float s = 0.f, tv = 0.f;
            for (int jx = lane; jx < N; jx += 32) {
                float x = logits[jx];
                s += __expf(x - mx);
                if (jx == tgt) tv = x;
            }
            for (int o = 16; o; o >>= 1) s  += __shfl_xor_sync(0xffffffffu, s, o);
            for (int o = 16; o; o >>= 1) tv += __shfl_xor_sync(0xffffffffu, tv, o);

            float nll;
            if (self) {
                float rest = fmaxf(s - __expf(tv - mx), 0.0f);
                nll = __logf(1.0f + 0.36787944117144233f * rest);
            } else {
                nll = mx + __logf(s) - tv;
            }
            if (lane == 0) {
                atomicAdd(&sh_loss[dir], nll);
                if (dir == 0) atomicAdd(&sh_cnt, 1);
            }
        }
    }
    __syncthreads();
    block_epilogue(sh_loss[0], sh_loss[1], sh_cnt, w, out, gridDim.x);
}

extern "C" void kernel_launch(void* const* d_in, const int* in_sizes, int n_in,
                              void* d_out, int out_size) {
    const float*         slog = (const float*)d_in[0];
    const void*          slab = d_in[1];
    const float*         plog = (const float*)d_in[2];
    const void*          plab = d_in[3];
    const unsigned char* mask = (const unsigned char*)d_in[4];
    const float*         w    = (const float*)d_in[5];
    float*               out  = (float*)d_out;

    const long long total = (long long)in_sizes[0];   // B*N*N
    const int       BN    = in_sizes[1];              // B*N
    const int       N     = (int)(total / (long long)BN);

    init_kernel<<<1, 256>>>((const int*)slab, mask, BN);

    if ((N == 1024 || N == 512 || N == 2048) && (BN % TR == 0)) {
        const int ntiles = 2 * BN / TR;
        const int grid = (ntiles < G_BLOCKS) ? ntiles : G_BLOCKS;
        if (N == 1024)
            loss_kernel_tma<1024, 4><<<grid, TPB>>>(slog, slab, plog, plab, mask, BN, w, out, ntiles);
        else if (N == 2048)
            loss_kernel_tma<2048, 2><<<grid, TPB>>>(slog, slab, plog, plab, mask, BN, w, out, ntiles);
        else
            loss_kernel_tma<512, 4><<<grid, TPB>>>(slog, slab, plog, plab, mask, BN, w, out, ntiles);
    } else {
        const int totalWarps = 2 * BN;
        const int blocks = (totalWarps + 7) / 8;
        loss_kernel_generic<<<blocks, 256>>>(slog, slab, plog, plab, mask, N, BN, w, out);
    }
}

// round 12
// speedup vs baseline: 1.2162x; 1.2162x over previous
#include <cuda_runtime.h>
#include <cstdint>

#define TPB        256        // 8 warps: warp-pair per row, 4 rows per tile
#define TR         4          // rows per tile (16 KB tile @ N=1024)

__device__ double   g_loss[2];   // [0]=succ sum, [1]=pred sum
__device__ int      g_cnt;       // sum(line_mask)
__device__ int      g_lbl64;     // 1 if labels are int64, 0 if int32
__device__ int      g_mask32;    // 1 if mask is int32, 0 if uint8
__device__ unsigned g_done;      // completed-block ticket

// ---------------------------------------------------------------------------
// init: zero accumulators + detect label width (int64 vs int32) and mask
// width (int32 vs uint8). Parallel — the serial version cost 547us.
// ---------------------------------------------------------------------------
__global__ void __launch_bounds__(256)
init_kernel(const int* __restrict__ label_words,
            const unsigned char* __restrict__ mask_bytes,
            int BN) {
    __shared__ int sh_not64;
    __shared__ unsigned sh_any;
    __shared__ unsigned sh_odd;

    const int tid = threadIdx.x;
    if (tid == 0) {
        g_loss[0] = 0.0; g_loss[1] = 0.0;
        g_cnt = 0; g_done = 0u;
        sh_not64 = 0; sh_any = 0u; sh_odd = 0u;
    }
    __syncthreads();

    if (tid < 128) {
        int lo = label_words[2 * tid];
        int hi = label_words[2 * tid + 1];
        bool ok = (hi == 0 && lo >= 0) || (hi == -1 && lo == -1);
        if (!ok) atomicOr(&sh_not64, 1);
    }
    {
        const uint4* m4 = (const uint4*)mask_bytes;
        const int words4 = BN / 16;
        unsigned my_all = 0u, my_odd = 0u;
        for (int k = tid; k < words4; k += 256) {
            uint4 v = m4[k];
            unsigned all = v.x | v.y | v.z | v.w;
            my_all |= all;
            my_odd |= (all & 0xFFFFFF00u);
        }
        for (int o = 16; o; o >>= 1) {
            my_all |= __shfl_xor_sync(0xffffffffu, my_all, o);
            my_odd |= __shfl_xor_sync(0xffffffffu, my_odd, o);
        }
        if ((tid & 31) == 0) {
            if (my_all) atomicOr(&sh_any, 1u);
            if (my_odd) atomicOr(&sh_odd, 1u);
        }
    }
    __syncthreads();
    if (tid == 0) {
        g_lbl64  = sh_not64 ? 0 : 1;
        g_mask32 = (sh_any && !sh_odd) ? 1 : 0;
    }
}

// ------------------------- PTX helpers -------------------------------------
__device__ __forceinline__ uint32_t smem_u32(const void* p) {
    uint32_t a;
    asm("{ .reg .u64 t; cvta.to.shared.u64 t, %1; cvt.u32.u64 %0, t; }"
        : "=r"(a) : "l"(p));
    return a;
}
__device__ __forceinline__ void mbar_init(uint32_t a, uint32_t c) {
    asm volatile("mbarrier.init.shared.b64 [%0], %1;" :: "r"(a), "r"(c) : "memory");
}
__device__ __forceinline__ void mbar_expect_tx(uint32_t a, uint32_t tx) {
    asm volatile("mbarrier.arrive.expect_tx.shared.b64 _, [%0], %1;"
                 :: "r"(a), "r"(tx) : "memory");
}
__device__ __forceinline__ void mbar_wait(uint32_t a, uint32_t ph) {
    asm volatile(
        "{\n\t"
        ".reg .pred P;\n\t"
        "WAIT_%=:\n\t"
        "mbarrier.try_wait.parity.acquire.cta.shared::cta.b64 P, [%0], %1, 0x989680;\n\t"
        "@P bra.uni DONE_%=;\n\t"
        "bra.uni WAIT_%=;\n\t"
        "DONE_%=:\n\t"
        "}"
        :: "r"(a), "r"(ph) : "memory");
}
__device__ __forceinline__ void bulk_g2s(uint32_t dst, const void* src,
                                         uint32_t bytes, uint32_t mbar) {
    asm volatile(
        "cp.async.bulk.shared::cluster.global.mbarrier::complete_tx::bytes "
        "[%0], [%1], %2, [%3];"
        :: "r"(dst), "l"(src), "r"(bytes), "r"(mbar) : "memory");
}
__device__ __forceinline__ void fence_proxy_async_cta() {
    asm volatile("fence.proxy.async.shared::cta;" ::: "memory");
}

__device__ __forceinline__ void block_epilogue(float l0, float l1, int cnt,
                                               const float* w, float* out,
                                               unsigned nblocks) {
    if (threadIdx.x == 0) {
        if (l0 != 0.f) atomicAdd(&g_loss[0], (double)l0);
        if (l1 != 0.f) atomicAdd(&g_loss[1], (double)l1);
        if (cnt)       atomicAdd(&g_cnt, cnt);
        __threadfence();
        unsigned t = atomicAdd(&g_done, 1u);
        if (t == nblocks - 1u) {
            double denom = (g_cnt > 0) ? (double)g_cnt : 1.0;
            float succ = (float)(g_loss[0] / denom);
            float pred = (float)(g_loss[1] / denom);
            out[0] = succ + (*w) * pred;
            out[1] = succ;
            out[2] = pred;
            out[3] = (float)g_cnt;
        }
    }
}

// ---------------------------------------------------------------------------
// R12: R9's tile geometry (TR=4 rows = 16 KB tiles, 8 warps, HALF-row/warp,
// K2=4 — the amortization R10/R11 destroyed) + a THIRD stage via dynamic
// smem (3 x 16 KB = 48 KB). R9 analysis: with 2 stages each refill gets
// exactly one tile-period; blocks idle ~1us/tile copy-latency-bound. Now
// refills get 2 periods of slack. 4 blocks/SM (32 warps); compute per tile
// (~1.1us) still fits under the 85%-DRAM period (~1.4us).
// ---------------------------------------------------------------------------
template <int NCOLS, int NS>
__global__ void __launch_bounds__(TPB)
loss_kernel_tma(const float* __restrict__ slog, const void* __restrict__ slab,
                const float* __restrict__ plog, const void* __restrict__ plab,
                const unsigned char* __restrict__ mask, int BN,
                const float* __restrict__ w, float* __restrict__ out,
                int ntiles) {
    extern __shared__ __align__(16) float st[];   // [NS][TR][NCOLS]
    __shared__ __align__(8) unsigned long long mbar[NS];
    __shared__ float sh_sum[TPB / 32];
    __shared__ float sh_max[TPB / 32];
    __shared__ float sh_loss[2];
    __shared__ int   sh_cnt;

    const int tid  = threadIdx.x;
    const int wid  = tid >> 5;
    const int lane = tid & 31;
    const int j    = wid >> 1;      // row within tile (0..TR-1)
    const int half = wid & 1;

    constexpr int      K2         = NCOLS / 256;        // float4/lane/half
    constexpr uint32_t TILE_BYTES = TR * NCOLS * 4;
    const int tilesPerTensor = ntiles >> 1;

    uint32_t mb[NS], stb[NS];
#pragma unroll
    for (int s = 0; s < NS; s++) {
        mb[s]  = smem_u32(&mbar[s]);
        stb[s] = smem_u32(&st[s * (TR * NCOLS)]);
    }

    if (tid == 0) {
        sh_loss[0] = 0.f; sh_loss[1] = 0.f; sh_cnt = 0;
#pragma unroll
        for (int s = 0; s < NS; s++) mbar_init(mb[s], 1);
    }
    __syncthreads();

    const bool l64 = (g_lbl64 != 0);
    const bool m32 = (g_mask32 != 0);

    // prologue: fill all stages
    if (tid == 0) {
#pragma unroll
        for (int s = 0; s < NS; s++) {
            int t = blockIdx.x + s * (int)gridDim.x;
            if (t < ntiles) {
                const float* src = (t < tilesPerTensor)
                    ? slog + (size_t)t * (TR * NCOLS)
                    : plog + (size_t)(t - tilesPerTensor) * (TR * NCOLS);
                mbar_expect_tx(mb[s], TILE_BYTES);
                bulk_g2s(stb[s], src, TILE_BYTES, mb[s]);
            }
        }
    }

    int it = 0;
    for (int t = blockIdx.x; t < ntiles; t += gridDim.x, it++) {
        const int      s      = it % NS;
        const uint32_t parity = (uint32_t)((it / NS) & 1);
        float* tile = &st[s * (TR * NCOLS)];

        const int dir   = (t < tilesPerTensor) ? 0 : 1;
        const int rbase = (dir ? (t - tilesPerTensor) : t) * TR;
        const int r     = rbase + j;
        const int i     = r & (NCOLS - 1);

        // prefetch scalars BEFORE the stage wait
        int lbl;
        if (l64) lbl = (int)((const long long*)(dir ? plab : slab))[r];
        else     lbl = ((const int*)(dir ? plab : slab))[r];
        const bool active = m32 ? (((const int*)mask)[r] != 0) : (mask[r] != 0);
        const bool self   = active && (lbl < 0);

        mbar_wait(mb[s], parity);

        // target logit from smem (row is staged)
        float tvx = 0.f;
        if (active && half == 0 && lane == 0)
            tvx = tile[j * NCOLS + ((lbl < 0) ? i : lbl)];

        const float4* rp =
            reinterpret_cast<const float4*>(&tile[j * NCOLS + half * (NCOLS / 2)]);

        // ---- pass 1 partials (half-row per warp) ----
        if (active) {
            if (!self) {
                float s0 = 0.f, s1 = 0.f;
#pragma unroll
                for (int k = 0; k < K2; k++) {
                    float4 v = rp[k * 32 + lane];
                    s0 += __expf(v.x) + __expf(v.y);
                    s1 += __expf(v.z) + __expf(v.w);
                }
                float ss = s0 + s1;
#pragma unroll
                for (int o = 16; o; o >>= 1)
                    ss += __shfl_xor_sync(0xffffffffu, ss, o);
                if (lane == 0) sh_sum[wid] = ss;
            } else {
                float mx = -3.402823466e38f;
#pragma unroll
                for (int k = 0; k < K2; k++) {
                    float4 v = rp[k * 32 + lane];
                    mx = fmaxf(mx, fmaxf(fmaxf(v.x, v.y), fmaxf(v.z, v.w)));
                }
#pragma unroll
                for (int o = 16; o; o >>= 1)
                    mx = fmaxf(mx, __shfl_xor_sync(0xffffffffu, mx, o));
                if (lane == 0) sh_max[wid] = mx;
            }
        }
        __syncthreads();   // sync1

        // ---- pass 2: self rows, shifted sum with combined row max ----
        if (self) {
            float mx = fmaxf(sh_max[wid & ~1], sh_max[wid | 1]);
            float ss = 0.f;
#pragma unroll
            for (int k = 0; k < K2; k++) {
                float4 v = rp[k * 32 + lane];
                ss += __expf(v.x - mx) + __expf(v.y - mx) +
                      __expf(v.z - mx) + __expf(v.w - mx);
            }
#pragma unroll
            for (int o = 16; o; o >>= 1)
                ss += __shfl_xor_sync(0xffffffffu, ss, o);
            if (lane == 0) sh_sum[wid] = ss;
        }
        __syncthreads();   // sync2 — stage s fully consumed

        // ---- refill stage s with tile t + NS*gridDim.x ----
        if (tid == 0) {
            int t2 = t + NS * (int)gridDim.x;
            if (t2 < ntiles) {
                const float* src = (t2 < tilesPerTensor)
                    ? slog + (size_t)t2 * (TR * NCOLS)
                    : plog + (size_t)(t2 - tilesPerTensor) * (TR * NCOLS);
                fence_proxy_async_cta();
                mbar_expect_tx(mb[s], TILE_BYTES);
                bulk_g2s(stb[s], src, TILE_BYTES, mb[s]);
            }
        }

        // ---- even warp of each pair finalizes (reads only sh_sum/sh_max) --
        if (active && half == 0 && lane == 0) {
            float S = sh_sum[wid] + sh_sum[wid + 1];
            float nll;
            if (!self) {
                nll = __logf(S) - tvx;
            } else {
                float mx = fmaxf(sh_max[wid], sh_max[wid + 1]);
                // diagonal := rowmax+1, label := i:
                // nll = log(1 + e^{-1} * (S - e^{x_i - M}))
                float rest = fmaxf(S - __expf(tvx - mx), 0.0f);
                nll = __logf(1.0f + 0.36787944117144233f * rest);
            }
            atomicAdd(&sh_loss[dir], nll);
            if (dir == 0) atomicAdd(&sh_cnt, 1);
        }
        // next iteration's mbar_wait + sync1 order everything else
    }
    __syncthreads();
    block_epilogue(sh_loss[0], sh_loss[1], sh_cnt, w, out, gridDim.x);
}

// ---------------------------------------------------------------------------
// Generic fallback (any N): two strided passes via global loads.
// ---------------------------------------------------------------------------
__global__ void __launch_bounds__(256)
loss_kernel_generic(const float* __restrict__ slog, const void* __restrict__ slab,
                    const float* __restrict__ plog, const void* __restrict__ plab,
                    const unsigned char* __restrict__ mask, int N, int BN,
                    const float* __restrict__ w, float* __restrict__ out) {
    __shared__ float sh_loss[2];
    __shared__ int   sh_cnt;
    if (threadIdx.x == 0) { sh_loss[0] = 0.f; sh_loss[1] = 0.f; sh_cnt = 0; }
    __syncthreads();

    const int lane = threadIdx.x & 31;
    const int warp = blockIdx.x * 8 + (threadIdx.x >> 5);

    if (warp < 2 * BN) {
        const int dir = (warp >= BN) ? 1 : 0;
        const int r   = dir ? warp - BN : warp;
        const int i   = r % N;

        const float* logits = (dir ? plog : slog) + (size_t)r * N;
        int lbl;
        if (g_lbl64) lbl = (int)((const long long*)(dir ? plab : slab))[r];
        else         lbl = ((const int*)(dir ? plab : slab))[r];
        const bool active = g_mask32 ? (((const int*)mask)[r] != 0) : (mask[r] != 0);

        if (active) {
            const bool self = (lbl < 0);
            const int  tgt  = self ? i : lbl;

            float mx = -3.402823466e38f;
            for (int jx = lane; jx < N; jx += 32) mx = fmaxf(mx, logits[jx]);
            for (int o = 16; o; o >>= 1)
                mx = fmaxf(mx, __shfl_xor_sync(0xffffffffu, mx, o));

            float s = 0.f, tv = 0.f;
            for (int jx = lane; jx < N; jx += 32) {
                float x = logits[jx];
                s += __expf(x - mx);
                if (jx == tgt) tv = x;
            }
            for (int o = 16; o; o >>= 1) s  += __shfl_xor_sync(0xffffffffu, s, o);
            for (int o = 16; o; o >>= 1) tv += __shfl_xor_sync(0xffffffffu, tv, o);

            float nll;
            if (self) {
                float rest = fmaxf(s - __expf(tv - mx), 0.0f);
                nll = __logf(1.0f + 0.36787944117144233f * rest);
            } else {
                nll = mx + __logf(s) - tv;
            }
            if (lane == 0) {
                atomicAdd(&sh_loss[dir], nll);
                if (dir == 0) atomicAdd(&sh_cnt, 1);
            }
        }
    }
    __syncthreads();
    block_epilogue(sh_loss[0], sh_loss[1], sh_cnt, w, out, gridDim.x);
}

extern "C" void kernel_launch(void* const* d_in, const int* in_sizes, int n_in,
                              void* d_out, int out_size) {
    const float*         slog = (const float*)d_in[0];
    const void*          slab = d_in[1];
    const float*         plog = (const float*)d_in[2];
    const void*          plab = d_in[3];
    const unsigned char* mask = (const unsigned char*)d_in[4];
    const float*         w    = (const float*)d_in[5];
    float*               out  = (float*)d_out;

    const long long total = (long long)in_sizes[0];   // B*N*N
    const int       BN    = in_sizes[1];              // B*N
    const int       N     = (int)(total / (long long)BN);

    init_kernel<<<1, 256>>>((const int*)slab, mask, BN);

    if ((N == 1024 || N == 512 || N == 2048) && (BN % TR == 0)) {
        const int ntiles = 2 * BN / TR;
        if (N == 1024) {
            constexpr int NS = 3;
            const size_t dyn = (size_t)NS * TR * 1024 * 4;   // 49152 B
            cudaFuncSetAttribute(loss_kernel_tma<1024, NS>,
                                 cudaFuncAttributeMaxDynamicSharedMemorySize,
                                 (int)dyn);
            const int grid = (ntiles < 592) ? ntiles : 592;  // 4 blocks/SM
            loss_kernel_tma<1024, NS><<<grid, TPB, dyn>>>(
                slog, slab, plog, plab, mask, BN, w, out, ntiles);
        } else if (N == 512) {
            constexpr int NS = 3;
            const size_t dyn = (size_t)NS * TR * 512 * 4;    // 24576 B
            const int grid = (ntiles < 1184) ? ntiles : 1184; // 8 blocks/SM
            loss_kernel_tma<512, NS><<<grid, TPB, dyn>>>(
                slog, slab, plog, plab, mask, BN, w, out, ntiles);
        } else {
            constexpr int NS = 2;
            const size_t dyn = (size_t)NS * TR * 2048 * 4;   // 65536 B
            cudaFuncSetAttribute(loss_kernel_tma<2048, NS>,
                                 cudaFuncAttributeMaxDynamicSharedMemorySize,
                                 (int)dyn);
            const int grid = (ntiles < 444) ? ntiles : 444;  // 3 blocks/SM
            loss_kernel_tma<2048, NS><<<grid, TPB, dyn>>>(
                slog, slab, plog, plab, mask, BN, w, out, ntiles);
        }
    } else {
        const int totalWarps = 2 * BN;
        const int blocks = (totalWarps + 7) / 8;
        loss_kernel_generic<<<blocks, 256>>>(slog, slab, plog, plab, mask, N, BN, w, out);
    }
}

// round 13
// speedup vs baseline: 1.2712x; 1.0452x over previous
#include <cuda_runtime.h>
#include <cstdint>

#define TPB        256
#define TR         4          // rows per tile (16 KB @ N=1024)
#define G_BLOCKS   888        // 6 blocks/SM * 148 SMs

__device__ double   g_loss[2];   // [0]=succ sum, [1]=pred sum
__device__ int      g_cnt;       // sum(line_mask)
__device__ int      g_lbl64;     // 1 if labels are int64, 0 if int32
__device__ int      g_mask32;    // 1 if mask is int32, 0 if uint8
__device__ unsigned g_done;      // completed-block ticket

// ---------------------------------------------------------------------------
// init: zero accumulators + detect label width (int64 vs int32) and mask
// width (int32 vs uint8). Parallel — the serial version cost 547us.
// ---------------------------------------------------------------------------
__global__ void __launch_bounds__(256)
init_kernel(const int* __restrict__ label_words,
            const unsigned char* __restrict__ mask_bytes,
            int BN) {
    __shared__ int sh_not64;
    __shared__ unsigned sh_any;
    __shared__ unsigned sh_odd;

    const int tid = threadIdx.x;
    if (tid == 0) {
        g_loss[0] = 0.0; g_loss[1] = 0.0;
        g_cnt = 0; g_done = 0u;
        sh_not64 = 0; sh_any = 0u; sh_odd = 0u;
    }
    __syncthreads();

    if (tid < 128) {
        int lo = label_words[2 * tid];
        int hi = label_words[2 * tid + 1];
        bool ok = (hi == 0 && lo >= 0) || (hi == -1 && lo == -1);
        if (!ok) atomicOr(&sh_not64, 1);
    }
    {
        const uint4* m4 = (const uint4*)mask_bytes;
        const int words4 = BN / 16;
        unsigned my_all = 0u, my_odd = 0u;
        for (int k = tid; k < words4; k += 256) {
            uint4 v = m4[k];
            unsigned all = v.x | v.y | v.z | v.w;
            my_all |= all;
            my_odd |= (all & 0xFFFFFF00u);
        }
        for (int o = 16; o; o >>= 1) {
            my_all |= __shfl_xor_sync(0xffffffffu, my_all, o);
            my_odd |= __shfl_xor_sync(0xffffffffu, my_odd, o);
        }
        if ((tid & 31) == 0) {
            if (my_all) atomicOr(&sh_any, 1u);
            if (my_odd) atomicOr(&sh_odd, 1u);
        }
    }
    __syncthreads();
    if (tid == 0) {
        g_lbl64  = sh_not64 ? 0 : 1;
        g_mask32 = (sh_any && !sh_odd) ? 1 : 0;
    }
}

// ------------------------- PTX helpers -------------------------------------
__device__ __forceinline__ uint32_t smem_u32(const void* p) {
    uint32_t a;
    asm("{ .reg .u64 t; cvta.to.shared.u64 t, %1; cvt.u32.u64 %0, t; }"
        : "=r"(a) : "l"(p));
    return a;
}
__device__ __forceinline__ void mbar_init(uint32_t a, uint32_t c) {
    asm volatile("mbarrier.init.shared.b64 [%0], %1;" :: "r"(a), "r"(c) : "memory");
}
__device__ __forceinline__ void mbar_expect_tx(uint32_t a, uint32_t tx) {
    asm volatile("mbarrier.arrive.expect_tx.shared.b64 _, [%0], %1;"
                 :: "r"(a), "r"(tx) : "memory");
}
__device__ __forceinline__ void mbar_wait(uint32_t a, uint32_t ph) {
    asm volatile(
        "{\n\t"
        ".reg .pred P;\n\t"
        "WAIT_%=:\n\t"
        "mbarrier.try_wait.parity.acquire.cta.shared::cta.b64 P, [%0], %1, 0x989680;\n\t"
        "@P bra.uni DONE_%=;\n\t"
        "bra.uni WAIT_%=;\n\t"
        "DONE_%=:\n\t"
        "}"
        :: "r"(a), "r"(ph) : "memory");
}
__device__ __forceinline__ void bulk_g2s(uint32_t dst, const void* src,
                                         uint32_t bytes, uint32_t mbar) {
    asm volatile(
        "cp.async.bulk.shared::cluster.global.mbarrier::complete_tx::bytes "
        "[%0], [%1], %2, [%3];"
        :: "r"(dst), "l"(src), "r"(bytes), "r"(mbar) : "memory");
}
__device__ __forceinline__ void fence_proxy_async_cta() {
    asm volatile("fence.proxy.async.shared::cta;" ::: "memory");
}

__device__ __forceinline__ void block_epilogue(float l0, float l1, int cnt,
                                               const float* w, float* out,
                                               unsigned nblocks) {
    if (threadIdx.x == 0) {
        if (l0 != 0.f) atomicAdd(&g_loss[0], (double)l0);
        if (l1 != 0.f) atomicAdd(&g_loss[1], (double)l1);
        if (cnt)       atomicAdd(&g_cnt, cnt);
        __threadfence();
        unsigned t = atomicAdd(&g_done, 1u);
        if (t == nblocks - 1u) {
            double denom = (g_cnt > 0) ? (double)g_cnt : 1.0;
            float succ = (float)(g_loss[0] / denom);
            float pred = (float)(g_loss[1] / denom);
            out[0] = succ + (*w) * pred;
            out[1] = succ;
            out[2] = pred;
            out[3] = (float)g_cnt;
        }
    }
}

// ---------------------------------------------------------------------------
// R13 = R9 (best: 2-stage, 16 KB tiles, 8 warps, half-row/warp, 6 blocks/SM;
// R10/R11/R12 showed every perturbation of that geometry loses) + ONE-BARRIER
// fast path: warps publish a self-flag before sync1; for the 99.6% of tiles
// with no self-pointing row the tile is fully consumed after pass 1, so the
// refill is issued right after sync1 and sync2 is skipped entirely.
// ---------------------------------------------------------------------------
template <int NCOLS>
__global__ void __launch_bounds__(TPB)
loss_kernel_tma(const float* __restrict__ slog, const void* __restrict__ slab,
                const float* __restrict__ plog, const void* __restrict__ plab,
                const unsigned char* __restrict__ mask, int BN,
                const float* __restrict__ w, float* __restrict__ out,
                int ntiles) {
    __shared__ __align__(16) float st[2][TR][NCOLS];
    __shared__ __align__(8)  unsigned long long mbar[2];
    __shared__ float sh_sum[TPB / 32];
    __shared__ float sh_max[TPB / 32];
    __shared__ int   sh_self[TPB / 32];
    __shared__ float sh_loss[2];
    __shared__ int   sh_cnt;

    const int tid  = threadIdx.x;
    const int wid  = tid >> 5;
    const int lane = tid & 31;
    const int j    = wid >> 1;      // row within tile (0..TR-1)
    const int half = wid & 1;

    constexpr int      K2         = NCOLS / 256;        // float4/lane/half
    constexpr uint32_t TILE_BYTES = TR * NCOLS * 4;
    const int tilesPerTensor = ntiles >> 1;

    const uint32_t mb[2]  = { smem_u32(&mbar[0]), smem_u32(&mbar[1]) };
    const uint32_t stb[2] = { smem_u32(&st[0][0][0]), smem_u32(&st[1][0][0]) };

    if (tid == 0) {
        sh_loss[0] = 0.f; sh_loss[1] = 0.f; sh_cnt = 0;
        mbar_init(mb[0], 1);
        mbar_init(mb[1], 1);
    }
    __syncthreads();

    const bool l64 = (g_lbl64 != 0);
    const bool m32 = (g_mask32 != 0);

    // prologue: fill both stages
    if (tid == 0) {
#pragma unroll
        for (int s = 0; s < 2; s++) {
            int t = blockIdx.x + s * (int)gridDim.x;
            if (t < ntiles) {
                const float* src = (t < tilesPerTensor)
                    ? slog + (size_t)t * (TR * NCOLS)
                    : plog + (size_t)(t - tilesPerTensor) * (TR * NCOLS);
                mbar_expect_tx(mb[s], TILE_BYTES);
                bulk_g2s(stb[s], src, TILE_BYTES, mb[s]);
            }
        }
    }

    int it = 0;
    for (int t = blockIdx.x; t < ntiles; t += gridDim.x, it++) {
        const int      s      = it & 1;
        const uint32_t parity = (uint32_t)((it >> 1) & 1);

        const int dir   = (t < tilesPerTensor) ? 0 : 1;
        const int rbase = (dir ? (t - tilesPerTensor) : t) * TR;
        const int r     = rbase + j;
        const int i     = r & (NCOLS - 1);

        // prefetch scalars BEFORE the stage wait
        int lbl;
        if (l64) lbl = (int)((const long long*)(dir ? plab : slab))[r];
        else     lbl = ((const int*)(dir ? plab : slab))[r];
        const bool active = m32 ? (((const int*)mask)[r] != 0) : (mask[r] != 0);
        const bool self   = active && (lbl < 0);

        mbar_wait(mb[s], parity);

        // target logit from smem (row is staged)
        float tvx = 0.f;
        if (active && half == 0 && lane == 0)
            tvx = st[s][j][(lbl < 0) ? i : lbl];

        const float4* rp =
            reinterpret_cast<const float4*>(&st[s][j][half * (NCOLS / 2)]);

        // ---- pass 1 partials ----
        if (active && !self) {
            float s0 = 0.f, s1 = 0.f;
#pragma unroll
            for (int k = 0; k < K2; k++) {
                float4 v = rp[k * 32 + lane];
                s0 += __expf(v.x) + __expf(v.y);
                s1 += __expf(v.z) + __expf(v.w);
            }
            float ss = s0 + s1;
#pragma unroll
            for (int o = 16; o; o >>= 1)
                ss += __shfl_xor_sync(0xffffffffu, ss, o);
            if (lane == 0) sh_sum[wid] = ss;
        } else if (self) {
            float mx = -3.402823466e38f;
#pragma unroll
            for (int k = 0; k < K2; k++) {
                float4 v = rp[k * 32 + lane];
                mx = fmaxf(mx, fmaxf(fmaxf(v.x, v.y), fmaxf(v.z, v.w)));
            }
#pragma unroll
            for (int o = 16; o; o >>= 1)
                mx = fmaxf(mx, __shfl_xor_sync(0xffffffffu, mx, o));
            if (lane == 0) sh_max[wid] = mx;
        }
        if (lane == 0) sh_self[wid] = self ? 1 : 0;   // published pre-sync1
        __syncthreads();   // sync1 (every path)

        // uniform block-wide decision: does any row of this tile self-point?
        int anyself = 0;
#pragma unroll
        for (int k = 0; k < TPB / 32; k++) anyself |= sh_self[k];

        if (anyself) {
            // ---- rare path: pass 2 for self rows, then the second barrier --
            if (self) {
                float mx = fmaxf(sh_max[wid & ~1], sh_max[wid | 1]);
                float ss = 0.f;
#pragma unroll
                for (int k = 0; k < K2; k++) {
                    float4 v = rp[k * 32 + lane];
                    ss += __expf(v.x - mx) + __expf(v.y - mx) +
                          __expf(v.z - mx) + __expf(v.w - mx);
                }
#pragma unroll
                for (int o = 16; o; o >>= 1)
                    ss += __shfl_xor_sync(0xffffffffu, ss, o);
                if (lane == 0) sh_sum[wid] = ss;
            }
            __syncthreads();   // sync2 — only on self tiles
        }

        // ---- refill stage s (tile fully consumed at this point) ----
        if (tid == 0) {
            int t2 = t + 2 * (int)gridDim.x;
            if (t2 < ntiles) {
                const float* src = (t2 < tilesPerTensor)
                    ? slog + (size_t)t2 * (TR * NCOLS)
                    : plog + (size_t)(t2 - tilesPerTensor) * (TR * NCOLS);
                fence_proxy_async_cta();
                mbar_expect_tx(mb[s], TILE_BYTES);
                bulk_g2s(stb[s], src, TILE_BYTES, mb[s]);
            }
        }

        // ---- even warp of each pair finalizes (reads only sh_sum/sh_max) --
        if (active && half == 0 && lane == 0) {
            float S = sh_sum[wid] + sh_sum[wid + 1];
            float nll;
            if (!self) {
                nll = __logf(S) - tvx;
            } else {
                float mx = fmaxf(sh_max[wid], sh_max[wid + 1]);
                // diagonal := rowmax+1, label := i:
                // nll = log(1 + e^{-1} * (S - e^{x_i - M}))
                float rest = fmaxf(S - __expf(tvx - mx), 0.0f);
                nll = __logf(1.0f + 0.36787944117144233f * rest);
            }
            atomicAdd(&sh_loss[dir], nll);
            if (dir == 0) atomicAdd(&sh_cnt, 1);
        }
        // next iteration's mbar_wait orders the rest
    }
    __syncthreads();
    block_epilogue(sh_loss[0], sh_loss[1], sh_cnt, w, out, gridDim.x);
}

// ---------------------------------------------------------------------------
// Generic fallback (any N): two strided passes via global loads.
// ---------------------------------------------------------------------------
__global__ void __launch_bounds__(256)
loss_kernel_generic(const float* __restrict__ slog, const void* __restrict__ slab,
                    const float* __restrict__ plog, const void* __restrict__ plab,
                    const unsigned char* __restrict__ mask, int N, int BN,
                    const float* __restrict__ w, float* __restrict__ out) {
    __shared__ float sh_loss[2];
    __shared__ int   sh_cnt;
    if (threadIdx.x == 0) { sh_loss[0] = 0.f; sh_loss[1] = 0.f; sh_cnt = 0; }
    __syncthreads();

    const int lane = threadIdx.x & 31;
    const int warp = blockIdx.x * 8 + (threadIdx.x >> 5);

    if (warp < 2 * BN) {
        const int dir = (warp >= BN) ? 1 : 0;
        const int r   = dir ? warp - BN : warp;
        const int i   = r % N;

        const float* logits = (dir ? plog : slog) + (size_t)r * N;
        int lbl;
        if (g_lbl64) lbl = (int)((const long long*)(dir ? plab : slab))[r];
        else         lbl = ((const int*)(dir ? plab : slab))[r];
        const bool active = g_mask32 ? (((const int*)mask)[r] != 0) : (mask[r] != 0);

        if (active) {
            const bool self = (lbl < 0);
            const int  tgt  = self ? i : lbl;

            float mx = -3.402823466e38f;
            for (int jx = lane; jx < N; jx += 32) mx = fmaxf(mx, logits[jx]);
            for (int o = 16; o; o >>= 1)
                mx = fmaxf(mx, __shfl_xor_sync(0xffffffffu, mx, o));

            float s = 0.f, tv = 0.f;
            for (int jx = lane; jx < N; jx += 32) {
                float x = logits[jx];
                s += __expf(x - mx);
                if (jx == tgt) tv = x;
            }
            for (int o = 16; o; o >>= 1) s  += __shfl_xor_sync(0xffffffffu, s, o);
            for (int o = 16; o; o >>= 1) tv += __shfl_xor_sync(0xffffffffu, tv, o);

            float nll;
            if (self) {
                float rest = fmaxf(s - __expf(tv - mx), 0.0f);
                nll = __logf(1.0f + 0.36787944117144233f * rest);
            } else {
                nll = mx + __logf(s) - tv;
            }
            if (lane == 0) {
                atomicAdd(&sh_loss[dir], nll);
                if (dir == 0) atomicAdd(&sh_cnt, 1);
            }
        }
    }
    __syncthreads();
    block_epilogue(sh_loss[0], sh_loss[1], sh_cnt, w, out, gridDim.x);
}

extern "C" void kernel_launch(void* const* d_in, const int* in_sizes, int n_in,
                              void* d_out, int out_size) {
    const float*         slog = (const float*)d_in[0];
    const void*          slab = d_in[1];
    const float*         plog = (const float*)d_in[2];
    const void*          plab = d_in[3];
    const unsigned char* mask = (const unsigned char*)d_in[4];
    const float*         w    = (const float*)d_in[5];
    float*               out  = (float*)d_out;

    const long long total = (long long)in_sizes[0];   // B*N*N
    const int       BN    = in_sizes[1];              // B*N
    const int       N     = (int)(total / (long long)BN);

    init_kernel<<<1, 256>>>((const int*)slab, mask, BN);

    if ((N == 1024 || N == 512 || N == 2048) && (BN % TR == 0)) {
        const int ntiles = 2 * BN / TR;
        const int grid = (ntiles < G_BLOCKS) ? ntiles : G_BLOCKS;
        if (N == 1024)
            loss_kernel_tma<1024><<<grid, TPB>>>(slog, slab, plog, plab, mask, BN, w, out, ntiles);
        else if (N == 2048)
            loss_kernel_tma<2048><<<grid, TPB>>>(slog, slab, plog, plab, mask, BN, w, out, ntiles);
        else
            loss_kernel_tma<512><<<grid, TPB>>>(slog, slab, plog, plab, mask, BN, w, out, ntiles);
    } else {
        const int totalWarps = 2 * BN;
        const int blocks = (totalWarps + 7) / 8;
        loss_kernel_generic<<<blocks, 256>>>(slog, slab, plog, plab, mask, N, BN, w, out);
    }
}

// round 14
// speedup vs baseline: 1.2968x; 1.0202x over previous
#include <cuda_runtime.h>
#include <cstdint>

#define TPB        256
#define TR         4          // rows per tile (16 KB @ N=1024)
#define G_BLOCKS   888        // 6 blocks/SM * 148 SMs

__device__ double   g_loss[2];   // [0]=succ sum, [1]=pred sum (zero at load; self-reset)
__device__ int      g_cnt;       // sum(line_mask)
__device__ unsigned g_done;      // completed-block ticket

// ------------------------- PTX helpers -------------------------------------
__device__ __forceinline__ uint32_t smem_u32(const void* p) {
    uint32_t a;
    asm("{ .reg .u64 t; cvta.to.shared.u64 t, %1; cvt.u32.u64 %0, t; }"
        : "=r"(a) : "l"(p));
    return a;
}
__device__ __forceinline__ void mbar_init(uint32_t a, uint32_t c) {
    asm volatile("mbarrier.init.shared.b64 [%0], %1;" :: "r"(a), "r"(c) : "memory");
}
__device__ __forceinline__ void mbar_expect_tx(uint32_t a, uint32_t tx) {
    asm volatile("mbarrier.arrive.expect_tx.shared.b64 _, [%0], %1;"
                 :: "r"(a), "r"(tx) : "memory");
}
__device__ __forceinline__ void mbar_wait(uint32_t a, uint32_t ph) {
    asm volatile(
        "{\n\t"
        ".reg .pred P;\n\t"
        "WAIT_%=:\n\t"
        "mbarrier.try_wait.parity.acquire.cta.shared::cta.b64 P, [%0], %1, 0x989680;\n\t"
        "@P bra.uni DONE_%=;\n\t"
        "bra.uni WAIT_%=;\n\t"
        "DONE_%=:\n\t"
        "}"
        :: "r"(a), "r"(ph) : "memory");
}
__device__ __forceinline__ void bulk_g2s(uint32_t dst, const void* src,
                                         uint32_t bytes, uint32_t mbar) {
    asm volatile(
        "cp.async.bulk.shared::cluster.global.mbarrier::complete_tx::bytes "
        "[%0], [%1], %2, [%3];"
        :: "r"(dst), "l"(src), "r"(bytes), "r"(mbar) : "memory");
}
__device__ __forceinline__ void fence_proxy_async_cta() {
    asm volatile("fence.proxy.async.shared::cta;" ::: "memory");
}

// block epilogue: accumulate; last block writes outputs THEN RESETS the
// globals so the next (graph-replayed) execution starts from zero state.
__device__ __forceinline__ void block_epilogue(float l0, float l1, int cnt,
                                               const float* w, float* out,
                                               unsigned nblocks) {
    if (threadIdx.x == 0) {
        if (l0 != 0.f) atomicAdd(&g_loss[0], (double)l0);
        if (l1 != 0.f) atomicAdd(&g_loss[1], (double)l1);
        if (cnt)       atomicAdd(&g_cnt, cnt);
        __threadfence();
        unsigned t = atomicAdd(&g_done, 1u);
        if (t == nblocks - 1u) {
            double denom = (g_cnt > 0) ? (double)g_cnt : 1.0;
            float succ = (float)(g_loss[0] / denom);
            float pred = (float)(g_loss[1] / denom);
            out[0] = succ + (*w) * pred;
            out[1] = succ;
            out[2] = pred;
            out[3] = (float)g_cnt;
            // self-reset for the next execution
            g_loss[0] = 0.0;
            g_loss[1] = 0.0;
            g_cnt = 0;
            __threadfence();
            g_done = 0u;
        }
    }
}

// per-block dtype detection (all blocks compute identical answers).
// Labels: int64 in [-1,N) => odd 32-bit words are 0 (lo>=0) or -1 (lo==-1).
// Mask: int32 bools => every byte at offset %4 != 0 is zero; uint8 with any
// trues has nonzero odd-offset bytes. Scans first min(BN,16384) bytes
// (L2-resident after the first readers).
__device__ __forceinline__ void detect_dtypes(const void* slab,
                                              const unsigned char* mask,
                                              int BN, int tid,
                                              int* sh_not64, unsigned* sh_any,
                                              unsigned* sh_odd) {
    if (tid < 128) {
        const int* lw = (const int*)slab;
        int lo = lw[2 * tid];
        int hi = lw[2 * tid + 1];
        bool ok = (hi == 0 && lo >= 0) || (hi == -1 && lo == -1);
        if (!ok) atomicOr(sh_not64, 1);
    }
    const uint4* m4 = (const uint4*)mask;
    const int nb = (BN < 16384) ? BN : 16384;
    const int words4 = nb / 16;
    unsigned my_all = 0u, my_odd = 0u;
    for (int k = tid; k < words4; k += TPB) {
        uint4 v = m4[k];
        unsigned all = v.x | v.y | v.z | v.w;
        my_all |= all;
        my_odd |= (all & 0xFFFFFF00u);
    }
    for (int o = 16; o; o >>= 1) {
        my_all |= __shfl_xor_sync(0xffffffffu, my_all, o);
        my_odd |= __shfl_xor_sync(0xffffffffu, my_odd, o);
    }
    if ((tid & 31) == 0) {
        if (my_all) atomicOr(sh_any, 1u);
        if (my_odd) atomicOr(sh_odd, 1u);
    }
}

// ---------------------------------------------------------------------------
// R14 = R13 (best: 2-stage 16 KB tiles, 8 warps half-row/warp, 6 blocks/SM,
// one-barrier fast path for the 99.6% of tiles with no self-pointing row)
// MINUS the serial init kernel (~7us): dtype flags are computed per-block in
// the prologue (hidden under the first TMA copies) and the accumulator
// globals self-reset in the last block's epilogue.
// ---------------------------------------------------------------------------
template <int NCOLS>
__global__ void __launch_bounds__(TPB)
loss_kernel_tma(const float* __restrict__ slog, const void* __restrict__ slab,
                const float* __restrict__ plog, const void* __restrict__ plab,
                const unsigned char* __restrict__ mask, int BN,
                const float* __restrict__ w, float* __restrict__ out,
                int ntiles) {
    __shared__ __align__(16) float st[2][TR][NCOLS];
    __shared__ __align__(8)  unsigned long long mbar[2];
    __shared__ float sh_sum[TPB / 32];
    __shared__ float sh_max[TPB / 32];
    __shared__ int   sh_self[TPB / 32];
    __shared__ float sh_loss[2];
    __shared__ int   sh_cnt;
    __shared__ int      sh_not64;
    __shared__ unsigned sh_any, sh_odd;

    const int tid  = threadIdx.x;
    const int wid  = tid >> 5;
    const int lane = tid & 31;
    const int j    = wid >> 1;      // row within tile (0..TR-1)
    const int half = wid & 1;

    constexpr int      K2         = NCOLS / 256;        // float4/lane/half
    constexpr uint32_t TILE_BYTES = TR * NCOLS * 4;
    const int tilesPerTensor = ntiles >> 1;

    const uint32_t mb[2]  = { smem_u32(&mbar[0]), smem_u32(&mbar[1]) };
    const uint32_t stb[2] = { smem_u32(&st[0][0][0]), smem_u32(&st[1][0][0]) };

    if (tid == 0) {
        sh_loss[0] = 0.f; sh_loss[1] = 0.f; sh_cnt = 0;
        sh_not64 = 0; sh_any = 0u; sh_odd = 0u;
        mbar_init(mb[0], 1);
        mbar_init(mb[1], 1);
    }
    __syncthreads();

    // prologue: fill both stages FIRST (detection scan hides under these)
    if (tid == 0) {
#pragma unroll
        for (int s = 0; s < 2; s++) {
            int t = blockIdx.x + s * (int)gridDim.x;
            if (t < ntiles) {
                const float* src = (t < tilesPerTensor)
                    ? slog + (size_t)t * (TR * NCOLS)
                    : plog + (size_t)(t - tilesPerTensor) * (TR * NCOLS);
                mbar_expect_tx(mb[s], TILE_BYTES);
                bulk_g2s(stb[s], src, TILE_BYTES, mb[s]);
            }
        }
    }

    // per-block dtype detection (overlapped with the prologue copies)
    detect_dtypes(slab, mask, BN, tid, &sh_not64, &sh_any, &sh_odd);
    __syncthreads();
    const bool l64 = (sh_not64 == 0);
    const bool m32 = (sh_any && !sh_odd);

    int it = 0;
    for (int t = blockIdx.x; t < ntiles; t += gridDim.x, it++) {
        const int      s      = it & 1;
        const uint32_t parity = (uint32_t)((it >> 1) & 1);

        const int dir   = (t < tilesPerTensor) ? 0 : 1;
        const int rbase = (dir ? (t - tilesPerTensor) : t) * TR;
        const int r     = rbase + j;
        const int i     = r & (NCOLS - 1);

        // prefetch scalars BEFORE the stage wait
        int lbl;
        if (l64) lbl = (int)((const long long*)(dir ? plab : slab))[r];
        else     lbl = ((const int*)(dir ? plab : slab))[r];
        const bool active = m32 ? (((const int*)mask)[r] != 0) : (mask[r] != 0);
        const bool self   = active && (lbl < 0);

        mbar_wait(mb[s], parity);

        // target logit from smem (row is staged)
        float tvx = 0.f;
        if (active && half == 0 && lane == 0)
            tvx = st[s][j][(lbl < 0) ? i : lbl];

        const float4* rp =
            reinterpret_cast<const float4*>(&st[s][j][half * (NCOLS / 2)]);

        // ---- pass 1 partials ----
        if (active && !self) {
            float s0 = 0.f, s1 = 0.f;
#pragma unroll
            for (int k = 0; k < K2; k++) {
                float4 v = rp[k * 32 + lane];
                s0 += __expf(v.x) + __expf(v.y);
                s1 += __expf(v.z) + __expf(v.w);
            }
            float ss = s0 + s1;
#pragma unroll
            for (int o = 16; o; o >>= 1)
                ss += __shfl_xor_sync(0xffffffffu, ss, o);
            if (lane == 0) sh_sum[wid] = ss;
        } else if (self) {
            float mx = -3.402823466e38f;
#pragma unroll
            for (int k = 0; k < K2; k++) {
                float4 v = rp[k * 32 + lane];
                mx = fmaxf(mx, fmaxf(fmaxf(v.x, v.y), fmaxf(v.z, v.w)));
            }
#pragma unroll
            for (int o = 16; o; o >>= 1)
                mx = fmaxf(mx, __shfl_xor_sync(0xffffffffu, mx, o));
            if (lane == 0) sh_max[wid] = mx;
        }
        if (lane == 0) sh_self[wid] = self ? 1 : 0;   // published pre-sync1
        __syncthreads();   // sync1 (every path)

        // uniform block-wide decision: any self-pointing row in this tile?
        int anyself = 0;
#pragma unroll
        for (int k = 0; k < TPB / 32; k++) anyself |= sh_self[k];

        if (anyself) {
            // rare path: pass 2 for self rows, then the second barrier
            if (self) {
                float mx = fmaxf(sh_max[wid & ~1], sh_max[wid | 1]);
                float ss = 0.f;
#pragma unroll
                for (int k = 0; k < K2; k++) {
                    float4 v = rp[k * 32 + lane];
                    ss += __expf(v.x - mx) + __expf(v.y - mx) +
                          __expf(v.z - mx) + __expf(v.w - mx);
                }
#pragma unroll
                for (int o = 16; o; o >>= 1)
                    ss += __shfl_xor_sync(0xffffffffu, ss, o);
                if (lane == 0) sh_sum[wid] = ss;
            }
            __syncthreads();   // sync2 — only on self tiles
        }

        // ---- refill stage s (tile fully consumed at this point) ----
        if (tid == 0) {
            int t2 = t + 2 * (int)gridDim.x;
            if (t2 < ntiles) {
                const float* src = (t2 < tilesPerTensor)
                    ? slog + (size_t)t2 * (TR * NCOLS)
                    : plog + (size_t)(t2 - tilesPerTensor) * (TR * NCOLS);
                fence_proxy_async_cta();
                mbar_expect_tx(mb[s], TILE_BYTES);
                bulk_g2s(stb[s], src, TILE_BYTES, mb[s]);
            }
        }

        // ---- even warp of each pair finalizes (reads only sh_sum/sh_max) --
        if (active && half == 0 && lane == 0) {
            float S = sh_sum[wid] + sh_sum[wid + 1];
            float nll;
            if (!self) {
                nll = __logf(S) - tvx;
            } else {
                float mx = fmaxf(sh_max[wid], sh_max[wid + 1]);
                // diagonal := rowmax+1, label := i:
                // nll = log(1 + e^{-1} * (S - e^{x_i - M}))
                float rest = fmaxf(S - __expf(tvx - mx), 0.0f);
                nll = __logf(1.0f + 0.36787944117144233f * rest);
            }
            atomicAdd(&sh_loss[dir], nll);
            if (dir == 0) atomicAdd(&sh_cnt, 1);
        }
        // next iteration's mbar_wait orders the rest
    }
    __syncthreads();
    block_epilogue(sh_loss[0], sh_loss[1], sh_cnt, w, out, gridDim.x);
}

// ---------------------------------------------------------------------------
// Generic fallback (any N): two strided passes via global loads, with the
// same per-block detection + self-resetting epilogue.
// ---------------------------------------------------------------------------
__global__ void __launch_bounds__(256)
loss_kernel_generic(const float* __restrict__ slog, const void* __restrict__ slab,
                    const float* __restrict__ plog, const void* __restrict__ plab,
                    const unsigned char* __restrict__ mask, int N, int BN,
                    const float* __restrict__ w, float* __restrict__ out) {
    __shared__ float sh_loss[2];
    __shared__ int   sh_cnt;
    __shared__ int      sh_not64;
    __shared__ unsigned sh_any, sh_odd;
    const int tid = threadIdx.x;
    if (tid == 0) {
        sh_loss[0] = 0.f; sh_loss[1] = 0.f; sh_cnt = 0;
        sh_not64 = 0; sh_any = 0u; sh_odd = 0u;
    }
    __syncthreads();
    detect_dtypes(slab, mask, BN, tid, &sh_not64, &sh_any, &sh_odd);
    __syncthreads();
    const bool l64 = (sh_not64 == 0);
    const bool m32 = (sh_any && !sh_odd);

    const int lane = tid & 31;
    const int warp = blockIdx.x * 8 + (tid >> 5);

    if (warp < 2 * BN) {
        const int dir = (warp >= BN) ? 1 : 0;
        const int r   = dir ? warp - BN : warp;
        const int i   = r % N;

        const float* logits = (dir ? plog : slog) + (size_t)r * N;
        int lbl;
        if (l64) lbl = (int)((const long long*)(dir ? plab : slab))[r];
        else     lbl = ((const int*)(dir ? plab : slab))[r];
        const bool active = m32 ? (((const int*)mask)[r] != 0) : (mask[r] != 0);

        if (active) {
            const bool self = (lbl < 0);
            const int  tgt  = self ? i : lbl;

            float mx = -3.402823466e38f;
            for (int jx = lane; jx < N; jx += 32) mx = fmaxf(mx, logits[jx]);
            for (int o = 16; o; o >>= 1)
                mx = fmaxf(mx, __shfl_xor_sync(0xffffffffu, mx, o));

            float s = 0.f, tv = 0.f;
            for (int jx = lane; jx < N; jx += 32) {
                float x = logits[jx];
                s += __expf(x - mx);
                if (jx == tgt) tv = x;
            }
            for (int o = 16; o; o >>= 1) s  += __shfl_xor_sync(0xffffffffu, s, o);
            for (int o = 16; o; o >>= 1) tv += __shfl_xor_sync(0xffffffffu, tv, o);

            float nll;
            if (self) {
                float rest = fmaxf(s - __expf(tv - mx), 0.0f);
                nll = __logf(1.0f + 0.36787944117144233f * rest);
            } else {
                nll = mx + __logf(s) - tv;
            }
            if (lane == 0) {
                atomicAdd(&sh_loss[dir], nll);
                if (dir == 0) atomicAdd(&sh_cnt, 1);
            }
        }
    }
    __syncthreads();
    block_epilogue(sh_loss[0], sh_loss[1], sh_cnt, w, out, gridDim.x);
}

extern "C" void kernel_launch(void* const* d_in, const int* in_sizes, int n_in,
                              void* d_out, int out_size) {
    const float*         slog = (const float*)d_in[0];
    const void*          slab = d_in[1];
    const float*         plog = (const float*)d_in[2];
    const void*          plab = d_in[3];
    const unsigned char* mask = (const unsigned char*)d_in[4];
    const float*         w    = (const float*)d_in[5];
    float*               out  = (float*)d_out;

    const long long total = (long long)in_sizes[0];   // B*N*N
    const int       BN    = in_sizes[1];              // B*N
    const int       N     = (int)(total / (long long)BN);

    if ((N == 1024 || N == 512 || N == 2048) && (BN % TR == 0)) {
        const int ntiles = 2 * BN / TR;
        const int grid = (ntiles < G_BLOCKS) ? ntiles : G_BLOCKS;
        if (N == 1024)
            loss_kernel_tma<1024><<<grid, TPB>>>(slog, slab, plog, plab, mask, BN, w, out, ntiles);
        else if (N == 2048)
            loss_kernel_tma<2048><<<grid, TPB>>>(slog, slab, plog, plab, mask, BN, w, out, ntiles);
        else
            loss_kernel_tma<512><<<grid, TPB>>>(slog, slab, plog, plab, mask, BN, w, out, ntiles);
    } else {
        const int totalWarps = 2 * BN;
        const int blocks = (totalWarps + 7) / 8;
        loss_kernel_generic<<<blocks, 256>>>(slog, slab, plog, plab, mask, N, BN, w, out);
    }
}